// round 1
// baseline (speedup 1.0000x reference)
#include <cuda_runtime.h>

// ---------------------------------------------------------------------------
// MultiheadAttention: b=2, n=2048, c=1024, h=16, d=64
// out = softmax((XWq^T+bq)(XWk^T+bk)^T * d^-0.5) (XWv^T+bv) Wo^T + bo
//
// Round 1: fp32 SIMT baseline.
//   K1: QKV projection GEMMs (z=0,1,2) -> head-layout scratch [b,h,n,d]
//   K2: flash attention (online softmax), 64-query tiles per block
//   K3: output projection GEMM -> d_out
// ---------------------------------------------------------------------------

namespace {
constexpr int B_ = 2;
constexpr int N_ = 2048;
constexpr int C_ = 1024;
constexpr int H_ = 16;
constexpr int D_ = 64;
constexpr float SCALE_ = 0.125f;   // 64^-0.5
constexpr int PAD = 68;            // row pitch in floats: 16B-aligned float4, low conflicts
constexpr int ATTN_SMEM_BYTES = (4 * 64 * PAD + 192) * 4;  // Qs,Ks,Vs,Ss + m,l,corr
}

// Scratch (device globals: allocation-free per harness rules)
__device__ float g_Qh[B_ * H_ * N_ * D_];   // 16 MB
__device__ float g_Kh[B_ * H_ * N_ * D_];
__device__ float g_Vh[B_ * H_ * N_ * D_];
__device__ float g_AO[B_ * N_ * C_];        // attention output, [b,n,c] layout

// ---------------------------------------------------------------------------
// K1: Y = X @ W^T + bias, X:[4096,1024], W:[1024,1024] (row-major, torch Linear)
//     write into head layout g_{Q,K,V}h[((b*H+h)*N + i)*D + dd]
// 64x64 output tile, BK=16, 256 threads, 4x4 microtile per thread.
// ---------------------------------------------------------------------------
__global__ __launch_bounds__(256)
void mha_qkv_proj_kernel(const float* __restrict__ q, const float* __restrict__ k,
                         const float* __restrict__ v,
                         const float* __restrict__ wq, const float* __restrict__ bq,
                         const float* __restrict__ wk, const float* __restrict__ bk,
                         const float* __restrict__ wv, const float* __restrict__ bv)
{
    __shared__ float As[16 * PAD];
    __shared__ float Bs[16 * PAD];

    const float* X; const float* W; const float* bias; float* Y;
    if (blockIdx.z == 0)      { X = q; W = wq; bias = bq; Y = g_Qh; }
    else if (blockIdx.z == 1) { X = k; W = wk; bias = bk; Y = g_Kh; }
    else                      { X = v; W = wv; bias = bv; Y = g_Vh; }

    const int tid = threadIdx.x;
    const int tx = tid & 15, ty = tid >> 4;
    const int rowBase = blockIdx.y * 64;   // 0..4095
    const int colBase = blockIdx.x * 64;   // 0..1023

    float acc[4][4] = {};

    for (int k0 = 0; k0 < C_; k0 += 16) {
        #pragma unroll
        for (int l = 0; l < 4; l++) {
            int idx = tid + l * 256;            // 0..1023
            int r  = idx >> 4;                  // 0..63
            int kk = idx & 15;                  // 0..15
            As[kk * PAD + r] = X[(rowBase + r) * C_ + k0 + kk];
            Bs[kk * PAD + r] = W[(colBase + r) * C_ + k0 + kk];
        }
        __syncthreads();

        #pragma unroll
        for (int kk = 0; kk < 16; kk++) {
            float4 a4 = *reinterpret_cast<const float4*>(&As[kk * PAD + ty * 4]);
            float4 b4 = *reinterpret_cast<const float4*>(&Bs[kk * PAD + tx * 4]);
            float av[4] = {a4.x, a4.y, a4.z, a4.w};
            float bv4[4] = {b4.x, b4.y, b4.z, b4.w};
            #pragma unroll
            for (int r = 0; r < 4; r++)
                #pragma unroll
                for (int c = 0; c < 4; c++)
                    acc[r][c] = fmaf(av[r], bv4[c], acc[r][c]);
        }
        __syncthreads();
    }

    #pragma unroll
    for (int r = 0; r < 4; r++) {
        int row = rowBase + ty * 4 + r;
        int bb  = row >> 11;            // /2048
        int i   = row & (N_ - 1);
        #pragma unroll
        for (int c = 0; c < 4; c++) {
            int col = colBase + tx * 4 + c;
            int h   = col >> 6;
            int dd  = col & 63;
            Y[((bb * H_ + h) * N_ + i) * D_ + dd] = acc[r][c] + bias[col];
        }
    }
}

// ---------------------------------------------------------------------------
// K2: flash attention. One block = one (b,h) + one 64-query tile.
// 256 threads, 4x4 microtile; online softmax with m/l/corr rows in SMEM.
// ---------------------------------------------------------------------------
__global__ __launch_bounds__(256)
void mha_attn_kernel()
{
    extern __shared__ float sm[];
    float* Qs   = sm;                 // [64][PAD], transposed: Qs[d][i]
    float* Ks   = Qs + 64 * PAD;      // transposed: Ks[d][j]
    float* Vs   = Ks + 64 * PAD;      // Vs[j][d]
    float* Ss   = Vs + 64 * PAD;      // scores/probs [64][PAD]
    float* mrow = Ss + 64 * PAD;      // [64]
    float* lrow = mrow + 64;          // [64]
    float* crow = lrow + 64;          // [64]

    const int tid = threadIdx.x;
    const int tx = tid & 15, ty = tid >> 4;
    const int bh = blockIdx.y;        // b*H + h
    const int qt = blockIdx.x;        // query tile

    const float* Qp = g_Qh + (size_t)bh * N_ * D_ + qt * 64 * D_;
    const float* Kb = g_Kh + (size_t)bh * N_ * D_;
    const float* Vb = g_Vh + (size_t)bh * N_ * D_;

    #pragma unroll
    for (int l = 0; l < 16; l++) {
        int idx = tid + l * 256;          // 0..4095
        int i = idx >> 6, d = idx & 63;
        Qs[d * PAD + i] = Qp[idx];
    }
    if (tid < 64) { mrow[tid] = -1e30f; lrow[tid] = 0.0f; }
    float o[4][4] = {};
    __syncthreads();

    for (int kt = 0; kt < N_ / 64; kt++) {
        const float* Kp = Kb + kt * 64 * D_;
        const float* Vp = Vb + kt * 64 * D_;
        #pragma unroll
        for (int l = 0; l < 16; l++) {
            int idx = tid + l * 256;
            int j = idx >> 6, d = idx & 63;
            Ks[d * PAD + j] = Kp[idx];
            Vs[j * PAD + d] = Vp[idx];
        }
        __syncthreads();

        // S = (Q @ K^T) * scale  -> Ss
        float s[4][4] = {};
        #pragma unroll
        for (int d = 0; d < 64; d++) {
            float4 a4 = *reinterpret_cast<const float4*>(&Qs[d * PAD + ty * 4]);
            float4 b4 = *reinterpret_cast<const float4*>(&Ks[d * PAD + tx * 4]);
            float av[4] = {a4.x, a4.y, a4.z, a4.w};
            float bv4[4] = {b4.x, b4.y, b4.z, b4.w};
            #pragma unroll
            for (int r = 0; r < 4; r++)
                #pragma unroll
                for (int c = 0; c < 4; c++)
                    s[r][c] = fmaf(av[r], bv4[c], s[r][c]);
        }
        #pragma unroll
        for (int r = 0; r < 4; r++) {
            float4 sv = make_float4(s[r][0] * SCALE_, s[r][1] * SCALE_,
                                    s[r][2] * SCALE_, s[r][3] * SCALE_);
            *reinterpret_cast<float4*>(&Ss[(ty * 4 + r) * PAD + tx * 4]) = sv;
        }
        __syncthreads();

        // Online softmax: 4 threads per row (quad), shfl-reduce within quad.
        {
            int row  = tid >> 2;
            int quad = tid & 3;
            float* srow = &Ss[row * PAD + quad * 16];
            float pm = -1e30f;
            #pragma unroll
            for (int j = 0; j < 16; j++) pm = fmaxf(pm, srow[j]);
            pm = fmaxf(pm, __shfl_xor_sync(0xffffffffu, pm, 1));
            pm = fmaxf(pm, __shfl_xor_sync(0xffffffffu, pm, 2));
            float new_m = fmaxf(mrow[row], pm);
            float ps = 0.0f;
            #pragma unroll
            for (int j = 0; j < 16; j++) {
                float e = __expf(srow[j] - new_m);
                srow[j] = e;
                ps += e;
            }
            ps += __shfl_xor_sync(0xffffffffu, ps, 1);
            ps += __shfl_xor_sync(0xffffffffu, ps, 2);
            if (quad == 0) {
                float cr = __expf(mrow[row] - new_m);
                lrow[row] = lrow[row] * cr + ps;
                mrow[row] = new_m;
                crow[row] = cr;
            }
        }
        __syncthreads();

        // O = O*corr + P @ V
        #pragma unroll
        for (int r = 0; r < 4; r++) {
            float cr = crow[ty * 4 + r];
            #pragma unroll
            for (int c = 0; c < 4; c++) o[r][c] *= cr;
        }
        #pragma unroll
        for (int j = 0; j < 64; j++) {
            float4 v4 = *reinterpret_cast<const float4*>(&Vs[j * PAD + tx * 4]);
            float vv[4] = {v4.x, v4.y, v4.z, v4.w};
            #pragma unroll
            for (int r = 0; r < 4; r++) {
                float p = Ss[(ty * 4 + r) * PAD + j];
                #pragma unroll
                for (int c = 0; c < 4; c++)
                    o[r][c] = fmaf(p, vv[c], o[r][c]);
            }
        }
        __syncthreads();
    }

    const int b = bh >> 4;   // /H
    const int h = bh & 15;
    #pragma unroll
    for (int r = 0; r < 4; r++) {
        int i = qt * 64 + ty * 4 + r;
        float inv = 1.0f / lrow[ty * 4 + r];
        #pragma unroll
        for (int c = 0; c < 4; c++) {
            g_AO[((size_t)(b * N_ + i)) * C_ + h * 64 + tx * 4 + c] = o[r][c] * inv;
        }
    }
}

// ---------------------------------------------------------------------------
// K3: out = g_AO @ Wo^T + bo  (plain [4096,1024] output)
// ---------------------------------------------------------------------------
__global__ __launch_bounds__(256)
void mha_out_proj_kernel(const float* __restrict__ wo, const float* __restrict__ bo,
                         float* __restrict__ out)
{
    __shared__ float As[16 * PAD];
    __shared__ float Bs[16 * PAD];

    const int tid = threadIdx.x;
    const int tx = tid & 15, ty = tid >> 4;
    const int rowBase = blockIdx.y * 64;
    const int colBase = blockIdx.x * 64;

    float acc[4][4] = {};

    for (int k0 = 0; k0 < C_; k0 += 16) {
        #pragma unroll
        for (int l = 0; l < 4; l++) {
            int idx = tid + l * 256;
            int r  = idx >> 4;
            int kk = idx & 15;
            As[kk * PAD + r] = g_AO[(rowBase + r) * C_ + k0 + kk];
            Bs[kk * PAD + r] = wo[(colBase + r) * C_ + k0 + kk];
        }
        __syncthreads();

        #pragma unroll
        for (int kk = 0; kk < 16; kk++) {
            float4 a4 = *reinterpret_cast<const float4*>(&As[kk * PAD + ty * 4]);
            float4 b4 = *reinterpret_cast<const float4*>(&Bs[kk * PAD + tx * 4]);
            float av[4] = {a4.x, a4.y, a4.z, a4.w};
            float bv4[4] = {b4.x, b4.y, b4.z, b4.w};
            #pragma unroll
            for (int r = 0; r < 4; r++)
                #pragma unroll
                for (int c = 0; c < 4; c++)
                    acc[r][c] = fmaf(av[r], bv4[c], acc[r][c]);
        }
        __syncthreads();
    }

    #pragma unroll
    for (int r = 0; r < 4; r++) {
        int row = rowBase + ty * 4 + r;
        #pragma unroll
        for (int c = 0; c < 4; c++) {
            int col = colBase + tx * 4 + c;
            out[row * C_ + col] = acc[r][c] + bo[col];
        }
    }
}

// ---------------------------------------------------------------------------
extern "C" void kernel_launch(void* const* d_in, const int* in_sizes, int n_in,
                              void* d_out, int out_size)
{
    (void)in_sizes; (void)n_in; (void)out_size;
    const float* q  = (const float*)d_in[0];
    const float* k  = (const float*)d_in[1];
    const float* v  = (const float*)d_in[2];
    const float* wq = (const float*)d_in[3];
    const float* bq = (const float*)d_in[4];
    const float* wk = (const float*)d_in[5];
    const float* bk = (const float*)d_in[6];
    const float* wv = (const float*)d_in[7];
    const float* bv = (const float*)d_in[8];
    const float* wo = (const float*)d_in[9];
    const float* bo = (const float*)d_in[10];
    float* out = (float*)d_out;

    cudaFuncSetAttribute(mha_attn_kernel,
                         cudaFuncAttributeMaxDynamicSharedMemorySize, ATTN_SMEM_BYTES);

    dim3 gproj(C_ / 64, (B_ * N_) / 64, 3);   // 16 x 64 x 3
    mha_qkv_proj_kernel<<<gproj, 256>>>(q, k, v, wq, bq, wk, bk, wv, bv);

    dim3 gattn(N_ / 64, B_ * H_);             // 32 x 32
    mha_attn_kernel<<<gattn, 256, ATTN_SMEM_BYTES>>>();

    dim3 gout(C_ / 64, (B_ * N_) / 64);       // 16 x 64
    mha_out_proj_kernel<<<gout, 256>>>(wo, bo, out);
}

// round 3
// speedup vs baseline: 1.4646x; 1.4646x over previous
#include <cuda_runtime.h>
#include <cuda_bf16.h>
#include <cstdint>

// ---------------------------------------------------------------------------
// MultiheadAttention: b=2, n=2048, c=1024, h=16, d=64
// Round 3: mma.sync (HMMA) bf16x3 projection GEMMs; fp32 flash attention.
// (tcgen05 is unavailable: harness compiles to plain compute_100 PTX.)
// ---------------------------------------------------------------------------

namespace {
constexpr int B_ = 2;
constexpr int N_ = 2048;
constexpr int C_ = 1024;
constexpr int H_ = 16;
constexpr int D_ = 64;
constexpr float SCALE_ = 0.125f;
constexpr int PAD = 68;
constexpr int ATTN_SMEM_BYTES = (4 * 64 * PAD + 192) * 4;

// GEMM tiling
constexpr int BM = 128, BN = 128, KC = 32;
constexpr int PITCH_B = 80;                    // bytes per SMEM row (32 bf16 + 8 pad)
constexpr int TILE_B = BM * PITCH_B;           // 10240 bytes per tile
constexpr int GEMM_SMEM = 2 * 4 * TILE_B;      // 2 stages x {Ahi,Alo,Bhi,Blo} = 80 KB
}

// Scratch
__device__ float g_Qh[B_ * H_ * N_ * D_];
__device__ float g_Kh[B_ * H_ * N_ * D_];
__device__ float g_Vh[B_ * H_ * N_ * D_];
__device__ float g_AO[B_ * N_ * C_];

// ---------------------------------------------------------------------------
__device__ __forceinline__ uint32_t smem_u32(const void* p) {
    uint32_t a;
    asm("{ .reg .u64 t; cvta.to.shared.u64 t, %1; cvt.u32.u64 %0, t; }" : "=r"(a) : "l"(p));
    return a;
}
__device__ __forceinline__ void ldm_x4(uint32_t* r, uint32_t addr) {
    asm volatile("ldmatrix.sync.aligned.m8n8.x4.shared.b16 {%0,%1,%2,%3}, [%4];"
                 : "=r"(r[0]), "=r"(r[1]), "=r"(r[2]), "=r"(r[3]) : "r"(addr));
}
__device__ __forceinline__ void mma16816(float* c, const uint32_t* a, const uint32_t* b) {
    asm volatile(
        "mma.sync.aligned.m16n8k16.row.col.f32.bf16.bf16.f32 "
        "{%0,%1,%2,%3}, {%4,%5,%6,%7}, {%8,%9}, {%0,%1,%2,%3};"
        : "+f"(c[0]), "+f"(c[1]), "+f"(c[2]), "+f"(c[3])
        : "r"(a[0]), "r"(a[1]), "r"(a[2]), "r"(a[3]), "r"(b[0]), "r"(b[1]));
}
__device__ __forceinline__ uint32_t pack_bf16(float a, float b) {
    __nv_bfloat162 t = __floats2bfloat162_rn(a, b);
    return *reinterpret_cast<uint32_t*>(&t);
}
__device__ __forceinline__ float bf_hi(float x) {
    return __bfloat162float(__float2bfloat16(x));
}
__device__ __forceinline__ void split_store(char* base, uint32_t off, float4 v) {
    float h0 = bf_hi(v.x), h1 = bf_hi(v.y), h2 = bf_hi(v.z), h3 = bf_hi(v.w);
    uint2 hi = make_uint2(pack_bf16(h0, h1), pack_bf16(h2, h3));
    uint2 lo = make_uint2(pack_bf16(v.x - h0, v.y - h1), pack_bf16(v.z - h2, v.w - h3));
    *reinterpret_cast<uint2*>(base + off) = hi;
    *reinterpret_cast<uint2*>(base + TILE_B + off) = lo;
}

// ---------------------------------------------------------------------------
// GEMM body: Y = X @ W^T + bias over a 128x128 tile.
// headLayout=true -> write to head-scratch layout [b,h,n,d]; else plain [row,col].
// ---------------------------------------------------------------------------
__device__ __forceinline__ void gemm_tile(const float* __restrict__ X,
                                          const float* __restrict__ W,
                                          const float* __restrict__ bias,
                                          float* __restrict__ Y,
                                          bool headLayout,
                                          int rowBase, int colBase, char* sm)
{
    const int tid = threadIdx.x;
    const int lane = tid & 31;
    const int wid = tid >> 5;
    const int warp_m = wid & 3;       // 4 warps in M
    const int warp_n = wid >> 2;      // 2 warps in N
    const uint32_t sbase = smem_u32(sm);

    float acc[2][8][4] = {};
    float4 xa[4], xb[4];

    // ldmatrix lane-address components
    const uint32_t aRow = (uint32_t)(warp_m * 32 + (lane & 15)) * PITCH_B + (uint32_t)(lane & 16);
    const uint32_t bRow = (uint32_t)(warp_n * 64 + ((lane & 7) | ((lane & 16) >> 1))) * PITCH_B
                          + (uint32_t)((lane & 8) * 2);

    // prologue: LDG + STS chunk 0
    #pragma unroll
    for (int l = 0; l < 4; l++) {
        int idx = tid + l * 256, r = idx >> 3, c4 = idx & 7;
        xa[l] = *reinterpret_cast<const float4*>(&X[(size_t)(rowBase + r) * C_ + c4 * 4]);
        xb[l] = *reinterpret_cast<const float4*>(&W[(size_t)(colBase + r) * C_ + c4 * 4]);
    }
    #pragma unroll
    for (int l = 0; l < 4; l++) {
        int idx = tid + l * 256, r = idx >> 3, c4 = idx & 7;
        uint32_t off = (uint32_t)(r * PITCH_B + c4 * 8);
        split_store(sm, off, xa[l]);                     // A -> tiles 0,1
        split_store(sm + 2 * TILE_B, off, xb[l]);        // B -> tiles 2,3
    }
    __syncthreads();

    for (int chunk = 0; chunk < C_ / KC; ++chunk) {
        // prefetch next chunk's globals
        if (chunk + 1 < C_ / KC) {
            const int k0 = (chunk + 1) * KC;
            #pragma unroll
            for (int l = 0; l < 4; l++) {
                int idx = tid + l * 256, r = idx >> 3, c4 = idx & 7;
                xa[l] = *reinterpret_cast<const float4*>(&X[(size_t)(rowBase + r) * C_ + k0 + c4 * 4]);
                xb[l] = *reinterpret_cast<const float4*>(&W[(size_t)(colBase + r) * C_ + k0 + c4 * 4]);
            }
        }

        // compute on stage chunk&1
        const uint32_t stB = sbase + (uint32_t)(chunk & 1) * (4 * TILE_B);
        #pragma unroll
        for (int ks = 0; ks < 2; ++ks) {
            uint32_t ah[2][4], al[2][4];
            ldm_x4(ah[0], stB + aRow + ks * 32);
            ldm_x4(ah[1], stB + aRow + 16 * PITCH_B + ks * 32);
            ldm_x4(al[0], stB + TILE_B + aRow + ks * 32);
            ldm_x4(al[1], stB + TILE_B + aRow + 16 * PITCH_B + ks * 32);
            #pragma unroll
            for (int t = 0; t < 4; ++t) {
                uint32_t bh[4], bl[4];
                ldm_x4(bh, stB + 2 * TILE_B + bRow + t * 16 * PITCH_B + ks * 32);
                ldm_x4(bl, stB + 3 * TILE_B + bRow + t * 16 * PITCH_B + ks * 32);
                #pragma unroll
                for (int f = 0; f < 2; ++f) {
                    #pragma unroll
                    for (int sub = 0; sub < 2; ++sub) {
                        float* c = acc[f][t * 2 + sub];
                        mma16816(c, ah[f], &bh[2 * sub]);
                        mma16816(c, ah[f], &bl[2 * sub]);
                        mma16816(c, al[f], &bh[2 * sub]);
                    }
                }
            }
        }

        // store next chunk into other stage
        if (chunk + 1 < C_ / KC) {
            char* dst = sm + ((chunk + 1) & 1) * (4 * TILE_B);
            #pragma unroll
            for (int l = 0; l < 4; l++) {
                int idx = tid + l * 256, r = idx >> 3, c4 = idx & 7;
                uint32_t off = (uint32_t)(r * PITCH_B + c4 * 8);
                split_store(dst, off, xa[l]);
                split_store(dst + 2 * TILE_B, off, xb[l]);
            }
        }
        __syncthreads();
    }

    // epilogue
    const int r = lane >> 2;
    const int cc = (lane & 3) * 2;
    #pragma unroll
    for (int f = 0; f < 2; ++f) {
        #pragma unroll
        for (int nf = 0; nf < 8; ++nf) {
            const float* c = acc[f][nf];
            const int col0 = colBase + warp_n * 64 + nf * 8 + cc;
            const int row0 = rowBase + warp_m * 32 + f * 16 + r;
            const float b0 = bias[col0], b1 = bias[col0 + 1];
            if (headLayout) {
                #pragma unroll
                for (int rr = 0; rr < 2; ++rr) {
                    const int row = row0 + rr * 8;
                    const int bb = row >> 11, i = row & (N_ - 1);
                    const int h = col0 >> 6, dd = col0 & 63;
                    float* p = &Y[((size_t)(bb * H_ + h) * N_ + i) * D_ + dd];
                    p[0] = c[rr * 2 + 0] + b0;
                    p[1] = c[rr * 2 + 1] + b1;
                }
            } else {
                #pragma unroll
                for (int rr = 0; rr < 2; ++rr) {
                    const int row = row0 + rr * 8;
                    float* p = &Y[(size_t)row * C_ + col0];
                    p[0] = c[rr * 2 + 0] + b0;
                    p[1] = c[rr * 2 + 1] + b1;
                }
            }
        }
    }
}

// ---------------------------------------------------------------------------
// K1: fused QKV projections (z selects Q/K/V)
// ---------------------------------------------------------------------------
__global__ __launch_bounds__(256, 1)
void mha_qkv_proj_kernel(const float* __restrict__ q, const float* __restrict__ k,
                         const float* __restrict__ v,
                         const float* __restrict__ wq, const float* __restrict__ bq,
                         const float* __restrict__ wk, const float* __restrict__ bk,
                         const float* __restrict__ wv, const float* __restrict__ bv)
{
    extern __shared__ __align__(16) char sm[];
    const float* X; const float* W; const float* bias; float* Y;
    if (blockIdx.z == 0)      { X = q; W = wq; bias = bq; Y = g_Qh; }
    else if (blockIdx.z == 1) { X = k; W = wk; bias = bk; Y = g_Kh; }
    else                      { X = v; W = wv; bias = bv; Y = g_Vh; }
    gemm_tile(X, W, bias, Y, true, blockIdx.y * BM, blockIdx.x * BN, sm);
}

// K3: output projection
__global__ __launch_bounds__(256, 1)
void mha_out_proj_kernel(const float* __restrict__ wo, const float* __restrict__ bo,
                         float* __restrict__ out)
{
    extern __shared__ __align__(16) char sm[];
    gemm_tile(g_AO, wo, bo, out, false, blockIdx.y * BM, blockIdx.x * BN, sm);
}

// ---------------------------------------------------------------------------
// K2: fp32 flash attention (unchanged)
// ---------------------------------------------------------------------------
__global__ __launch_bounds__(256)
void mha_attn_kernel()
{
    extern __shared__ float smf[];
    float* Qs   = smf;
    float* Ks   = Qs + 64 * PAD;
    float* Vs   = Ks + 64 * PAD;
    float* Ss   = Vs + 64 * PAD;
    float* mrow = Ss + 64 * PAD;
    float* lrow = mrow + 64;
    float* crow = lrow + 64;

    const int tid = threadIdx.x;
    const int tx = tid & 15, ty = tid >> 4;
    const int bh = blockIdx.y;
    const int qt = blockIdx.x;

    const float* Qp = g_Qh + (size_t)bh * N_ * D_ + qt * 64 * D_;
    const float* Kb = g_Kh + (size_t)bh * N_ * D_;
    const float* Vb = g_Vh + (size_t)bh * N_ * D_;

    #pragma unroll
    for (int l = 0; l < 16; l++) {
        int idx = tid + l * 256;
        int i = idx >> 6, d = idx & 63;
        Qs[d * PAD + i] = Qp[idx];
    }
    if (tid < 64) { mrow[tid] = -1e30f; lrow[tid] = 0.0f; }
    float o[4][4] = {};
    __syncthreads();

    for (int kt = 0; kt < N_ / 64; kt++) {
        const float* Kp = Kb + kt * 64 * D_;
        const float* Vp = Vb + kt * 64 * D_;
        #pragma unroll
        for (int l = 0; l < 16; l++) {
            int idx = tid + l * 256;
            int j = idx >> 6, d = idx & 63;
            Ks[d * PAD + j] = Kp[idx];
            Vs[j * PAD + d] = Vp[idx];
        }
        __syncthreads();

        float s[4][4] = {};
        #pragma unroll
        for (int d = 0; d < 64; d++) {
            float4 a4 = *reinterpret_cast<const float4*>(&Qs[d * PAD + ty * 4]);
            float4 b4 = *reinterpret_cast<const float4*>(&Ks[d * PAD + tx * 4]);
            float av[4] = {a4.x, a4.y, a4.z, a4.w};
            float bv4[4] = {b4.x, b4.y, b4.z, b4.w};
            #pragma unroll
            for (int r = 0; r < 4; r++)
                #pragma unroll
                for (int c = 0; c < 4; c++)
                    s[r][c] = fmaf(av[r], bv4[c], s[r][c]);
        }
        #pragma unroll
        for (int r = 0; r < 4; r++) {
            float4 sv = make_float4(s[r][0] * SCALE_, s[r][1] * SCALE_,
                                    s[r][2] * SCALE_, s[r][3] * SCALE_);
            *reinterpret_cast<float4*>(&Ss[(ty * 4 + r) * PAD + tx * 4]) = sv;
        }
        __syncthreads();

        {
            int row  = tid >> 2;
            int quad = tid & 3;
            float* srow = &Ss[row * PAD + quad * 16];
            float pm = -1e30f;
            #pragma unroll
            for (int j = 0; j < 16; j++) pm = fmaxf(pm, srow[j]);
            pm = fmaxf(pm, __shfl_xor_sync(0xffffffffu, pm, 1));
            pm = fmaxf(pm, __shfl_xor_sync(0xffffffffu, pm, 2));
            float new_m = fmaxf(mrow[row], pm);
            float ps = 0.0f;
            #pragma unroll
            for (int j = 0; j < 16; j++) {
                float e = __expf(srow[j] - new_m);
                srow[j] = e;
                ps += e;
            }
            ps += __shfl_xor_sync(0xffffffffu, ps, 1);
            ps += __shfl_xor_sync(0xffffffffu, ps, 2);
            if (quad == 0) {
                float cr = __expf(mrow[row] - new_m);
                lrow[row] = lrow[row] * cr + ps;
                mrow[row] = new_m;
                crow[row] = cr;
            }
        }
        __syncthreads();

        #pragma unroll
        for (int r = 0; r < 4; r++) {
            float cr = crow[ty * 4 + r];
            #pragma unroll
            for (int c = 0; c < 4; c++) o[r][c] *= cr;
        }
        #pragma unroll
        for (int j = 0; j < 64; j++) {
            float4 v4 = *reinterpret_cast<const float4*>(&Vs[j * PAD + tx * 4]);
            float vv[4] = {v4.x, v4.y, v4.z, v4.w};
            #pragma unroll
            for (int r = 0; r < 4; r++) {
                float p = Ss[(ty * 4 + r) * PAD + j];
                #pragma unroll
                for (int c = 0; c < 4; c++)
                    o[r][c] = fmaf(p, vv[c], o[r][c]);
            }
        }
        __syncthreads();
    }

    const int b = bh >> 4;
    const int h = bh & 15;
    #pragma unroll
    for (int r = 0; r < 4; r++) {
        int i = qt * 64 + ty * 4 + r;
        float inv = 1.0f / lrow[ty * 4 + r];
        #pragma unroll
        for (int c = 0; c < 4; c++) {
            g_AO[((size_t)(b * N_ + i)) * C_ + h * 64 + tx * 4 + c] = o[r][c] * inv;
        }
    }
}

// ---------------------------------------------------------------------------
extern "C" void kernel_launch(void* const* d_in, const int* in_sizes, int n_in,
                              void* d_out, int out_size)
{
    (void)in_sizes; (void)n_in; (void)out_size;
    const float* q  = (const float*)d_in[0];
    const float* k  = (const float*)d_in[1];
    const float* v  = (const float*)d_in[2];
    const float* wq = (const float*)d_in[3];
    const float* bq = (const float*)d_in[4];
    const float* wk = (const float*)d_in[5];
    const float* bk = (const float*)d_in[6];
    const float* wv = (const float*)d_in[7];
    const float* bv = (const float*)d_in[8];
    const float* wo = (const float*)d_in[9];
    const float* bo = (const float*)d_in[10];
    float* out = (float*)d_out;

    cudaFuncSetAttribute(mha_qkv_proj_kernel,
                         cudaFuncAttributeMaxDynamicSharedMemorySize, GEMM_SMEM);
    cudaFuncSetAttribute(mha_out_proj_kernel,
                         cudaFuncAttributeMaxDynamicSharedMemorySize, GEMM_SMEM);
    cudaFuncSetAttribute(mha_attn_kernel,
                         cudaFuncAttributeMaxDynamicSharedMemorySize, ATTN_SMEM_BYTES);

    dim3 gproj(C_ / BN, (B_ * N_) / BM, 3);   // 8 x 32 x 3
    mha_qkv_proj_kernel<<<gproj, 256, GEMM_SMEM>>>(q, k, v, wq, bq, wk, bk, wv, bv);

    dim3 gattn(N_ / 64, B_ * H_);             // 32 x 32
    mha_attn_kernel<<<gattn, 256, ATTN_SMEM_BYTES>>>();

    dim3 gout(C_ / BN, (B_ * N_) / BM);       // 8 x 32
    mha_out_proj_kernel<<<gout, 256, GEMM_SMEM>>>(wo, bo, out);
}

// round 4
// speedup vs baseline: 2.8066x; 1.9164x over previous
#include <cuda_runtime.h>
#include <cuda_bf16.h>
#include <cstdint>

// ---------------------------------------------------------------------------
// MultiheadAttention: b=2, n=2048, c=1024, h=16, d=64
// Round 4: tensor-core (mma.sync bf16x3) flash attention + bf16x3 projections.
// ---------------------------------------------------------------------------

namespace {
constexpr int B_ = 2;
constexpr int N_ = 2048;
constexpr int C_ = 1024;
constexpr int H_ = 16;
constexpr int D_ = 64;
constexpr float QSCALE = 0.125f * 1.44269504088896340736f;  // scale * log2(e)

// GEMM tiling (round-3 proven)
constexpr int BM = 128, BN = 128, KC = 32;
constexpr int PITCH_B = 80;
constexpr int TILE_B = BM * PITCH_B;
constexpr int GEMM_SMEM = 2 * 4 * TILE_B;

// Attention tiling
constexpr int APITCH = 144;                    // 64 bf16 (128B) + 16B pad
constexpr int AHALF = 128 * APITCH;            // 18432 B: one 128x64 bf16 tile
constexpr int KV_STAGE = 4 * AHALF;            // Khi,Klo,Vhi,Vlo = 73728 B
constexpr int ATTN_SMEM = 2 * AHALF + 2 * KV_STAGE;  // Q + 2 KV stages = 184320
}

// Scratch
__device__ __nv_bfloat16 g_Qhi[B_ * H_ * N_ * D_];
__device__ __nv_bfloat16 g_Qlo[B_ * H_ * N_ * D_];
__device__ __nv_bfloat16 g_Khi[B_ * H_ * N_ * D_];
__device__ __nv_bfloat16 g_Klo[B_ * H_ * N_ * D_];
__device__ __nv_bfloat16 g_Vhi[B_ * H_ * N_ * D_];
__device__ __nv_bfloat16 g_Vlo[B_ * H_ * N_ * D_];
__device__ float g_AO[B_ * N_ * C_];

// ---------------------------------------------------------------------------
__device__ __forceinline__ uint32_t smem_u32(const void* p) {
    uint32_t a;
    asm("{ .reg .u64 t; cvta.to.shared.u64 t, %1; cvt.u32.u64 %0, t; }" : "=r"(a) : "l"(p));
    return a;
}
__device__ __forceinline__ void ldm_x4(uint32_t* r, uint32_t addr) {
    asm volatile("ldmatrix.sync.aligned.m8n8.x4.shared.b16 {%0,%1,%2,%3}, [%4];"
                 : "=r"(r[0]), "=r"(r[1]), "=r"(r[2]), "=r"(r[3]) : "r"(addr));
}
__device__ __forceinline__ void ldm_x4_t(uint32_t* r, uint32_t addr) {
    asm volatile("ldmatrix.sync.aligned.m8n8.x4.trans.shared.b16 {%0,%1,%2,%3}, [%4];"
                 : "=r"(r[0]), "=r"(r[1]), "=r"(r[2]), "=r"(r[3]) : "r"(addr));
}
__device__ __forceinline__ void mma16816(float* c, const uint32_t* a, const uint32_t* b) {
    asm volatile(
        "mma.sync.aligned.m16n8k16.row.col.f32.bf16.bf16.f32 "
        "{%0,%1,%2,%3}, {%4,%5,%6,%7}, {%8,%9}, {%0,%1,%2,%3};"
        : "+f"(c[0]), "+f"(c[1]), "+f"(c[2]), "+f"(c[3])
        : "r"(a[0]), "r"(a[1]), "r"(a[2]), "r"(a[3]), "r"(b[0]), "r"(b[1]));
}
__device__ __forceinline__ uint32_t pack_bf16(float a, float b) {
    __nv_bfloat162 t = __floats2bfloat162_rn(a, b);
    return *reinterpret_cast<uint32_t*>(&t);
}
__device__ __forceinline__ float bf_hi(float x) {
    return __bfloat162float(__float2bfloat16(x));
}
__device__ __forceinline__ void split2(float a, float b, uint32_t& hi, uint32_t& lo) {
    uint32_t h = pack_bf16(a, b);
    float ha = __uint_as_float(h << 16);
    float hb = __uint_as_float(h & 0xffff0000u);
    lo = pack_bf16(a - ha, b - hb);
    hi = h;
}
__device__ __forceinline__ float ex2f(float x) {
    float y;
    asm("ex2.approx.ftz.f32 %0, %1;" : "=f"(y) : "f"(x));
    return y;
}
__device__ __forceinline__ void cpa16(uint32_t dst, const void* src) {
    asm volatile("cp.async.cg.shared.global [%0], [%1], 16;" :: "r"(dst), "l"(src));
}
__device__ __forceinline__ void cp_commit() {
    asm volatile("cp.async.commit_group;" ::: "memory");
}
template <int n> __device__ __forceinline__ void cp_wait() {
    asm volatile("cp.async.wait_group %0;" :: "n"(n) : "memory");
}
__device__ __forceinline__ void split_store(char* base, uint32_t off, float4 v) {
    float h0 = bf_hi(v.x), h1 = bf_hi(v.y), h2 = bf_hi(v.z), h3 = bf_hi(v.w);
    uint2 hi = make_uint2(pack_bf16(h0, h1), pack_bf16(h2, h3));
    uint2 lo = make_uint2(pack_bf16(v.x - h0, v.y - h1), pack_bf16(v.z - h2, v.w - h3));
    *reinterpret_cast<uint2*>(base + off) = hi;
    *reinterpret_cast<uint2*>(base + TILE_B + off) = lo;
}

// ---------------------------------------------------------------------------
// GEMM tile (round-3 core). headLayout: write bf16 hi/lo head-scratch (+scale).
// ---------------------------------------------------------------------------
__device__ __forceinline__ void gemm_tile(const float* __restrict__ X,
                                          const float* __restrict__ W,
                                          const float* __restrict__ bias,
                                          float* __restrict__ Yf32,
                                          __nv_bfloat16* __restrict__ Yhi,
                                          __nv_bfloat16* __restrict__ Ylo,
                                          float oscale,
                                          int rowBase, int colBase, char* sm)
{
    const int tid = threadIdx.x;
    const int lane = tid & 31;
    const int wid = tid >> 5;
    const int warp_m = wid & 3;
    const int warp_n = wid >> 2;
    const uint32_t sbase = smem_u32(sm);

    float acc[2][8][4] = {};
    float4 xa[4], xb[4];

    const uint32_t aRow = (uint32_t)(warp_m * 32 + (lane & 15)) * PITCH_B + (uint32_t)(lane & 16);
    const uint32_t bRow = (uint32_t)(warp_n * 64 + ((lane & 7) | ((lane & 16) >> 1))) * PITCH_B
                          + (uint32_t)((lane & 8) * 2);

    #pragma unroll
    for (int l = 0; l < 4; l++) {
        int idx = tid + l * 256, r = idx >> 3, c4 = idx & 7;
        xa[l] = *reinterpret_cast<const float4*>(&X[(size_t)(rowBase + r) * C_ + c4 * 4]);
        xb[l] = *reinterpret_cast<const float4*>(&W[(size_t)(colBase + r) * C_ + c4 * 4]);
    }
    #pragma unroll
    for (int l = 0; l < 4; l++) {
        int idx = tid + l * 256, r = idx >> 3, c4 = idx & 7;
        uint32_t off = (uint32_t)(r * PITCH_B + c4 * 8);
        split_store(sm, off, xa[l]);
        split_store(sm + 2 * TILE_B, off, xb[l]);
    }
    __syncthreads();

    for (int chunk = 0; chunk < C_ / KC; ++chunk) {
        if (chunk + 1 < C_ / KC) {
            const int k0 = (chunk + 1) * KC;
            #pragma unroll
            for (int l = 0; l < 4; l++) {
                int idx = tid + l * 256, r = idx >> 3, c4 = idx & 7;
                xa[l] = *reinterpret_cast<const float4*>(&X[(size_t)(rowBase + r) * C_ + k0 + c4 * 4]);
                xb[l] = *reinterpret_cast<const float4*>(&W[(size_t)(colBase + r) * C_ + k0 + c4 * 4]);
            }
        }

        const uint32_t stB = sbase + (uint32_t)(chunk & 1) * (4 * TILE_B);
        #pragma unroll
        for (int ks = 0; ks < 2; ++ks) {
            uint32_t ah[2][4], al[2][4];
            ldm_x4(ah[0], stB + aRow + ks * 32);
            ldm_x4(ah[1], stB + aRow + 16 * PITCH_B + ks * 32);
            ldm_x4(al[0], stB + TILE_B + aRow + ks * 32);
            ldm_x4(al[1], stB + TILE_B + aRow + 16 * PITCH_B + ks * 32);
            #pragma unroll
            for (int t = 0; t < 4; ++t) {
                uint32_t bh[4], bl[4];
                ldm_x4(bh, stB + 2 * TILE_B + bRow + t * 16 * PITCH_B + ks * 32);
                ldm_x4(bl, stB + 3 * TILE_B + bRow + t * 16 * PITCH_B + ks * 32);
                #pragma unroll
                for (int f = 0; f < 2; ++f) {
                    #pragma unroll
                    for (int sub = 0; sub < 2; ++sub) {
                        float* c = acc[f][t * 2 + sub];
                        mma16816(c, ah[f], &bh[2 * sub]);
                        mma16816(c, ah[f], &bl[2 * sub]);
                        mma16816(c, al[f], &bh[2 * sub]);
                    }
                }
            }
        }

        if (chunk + 1 < C_ / KC) {
            char* dst = sm + ((chunk + 1) & 1) * (4 * TILE_B);
            #pragma unroll
            for (int l = 0; l < 4; l++) {
                int idx = tid + l * 256, r = idx >> 3, c4 = idx & 7;
                uint32_t off = (uint32_t)(r * PITCH_B + c4 * 8);
                split_store(dst, off, xa[l]);
                split_store(dst + 2 * TILE_B, off, xb[l]);
            }
        }
        __syncthreads();
    }

    const int r = lane >> 2;
    const int cc = (lane & 3) * 2;
    #pragma unroll
    for (int f = 0; f < 2; ++f) {
        #pragma unroll
        for (int nf = 0; nf < 8; ++nf) {
            const float* c = acc[f][nf];
            const int col0 = colBase + warp_n * 64 + nf * 8 + cc;
            const int row0 = rowBase + warp_m * 32 + f * 16 + r;
            const float b0 = bias[col0], b1 = bias[col0 + 1];
            if (Yhi) {
                #pragma unroll
                for (int rr = 0; rr < 2; ++rr) {
                    const int row = row0 + rr * 8;
                    const int bb = row >> 11, i = row & (N_ - 1);
                    const int h = col0 >> 6, dd = col0 & 63;
                    const size_t idx = ((size_t)(bb * H_ + h) * N_ + i) * D_ + dd;
                    float v0 = (c[rr * 2 + 0] + b0) * oscale;
                    float v1 = (c[rr * 2 + 1] + b1) * oscale;
                    uint32_t hi, lo;
                    split2(v0, v1, hi, lo);
                    *reinterpret_cast<uint32_t*>(&Yhi[idx]) = hi;
                    *reinterpret_cast<uint32_t*>(&Ylo[idx]) = lo;
                }
            } else {
                #pragma unroll
                for (int rr = 0; rr < 2; ++rr) {
                    const int row = row0 + rr * 8;
                    float* p = &Yf32[(size_t)row * C_ + col0];
                    p[0] = c[rr * 2 + 0] + b0;
                    p[1] = c[rr * 2 + 1] + b1;
                }
            }
        }
    }
}

__global__ __launch_bounds__(256, 1)
void mha_qkv_proj_kernel(const float* __restrict__ q, const float* __restrict__ k,
                         const float* __restrict__ v,
                         const float* __restrict__ wq, const float* __restrict__ bq,
                         const float* __restrict__ wk, const float* __restrict__ bk,
                         const float* __restrict__ wv, const float* __restrict__ bv)
{
    extern __shared__ __align__(16) char sm[];
    const float* X; const float* W; const float* bias;
    __nv_bfloat16 *Yhi, *Ylo; float sc;
    if (blockIdx.z == 0)      { X = q; W = wq; bias = bq; Yhi = g_Qhi; Ylo = g_Qlo; sc = QSCALE; }
    else if (blockIdx.z == 1) { X = k; W = wk; bias = bk; Yhi = g_Khi; Ylo = g_Klo; sc = 1.0f; }
    else                      { X = v; W = wv; bias = bv; Yhi = g_Vhi; Ylo = g_Vlo; sc = 1.0f; }
    gemm_tile(X, W, bias, nullptr, Yhi, Ylo, sc, blockIdx.y * BM, blockIdx.x * BN, sm);
}

__global__ __launch_bounds__(256, 1)
void mha_out_proj_kernel(const float* __restrict__ wo, const float* __restrict__ bo,
                         float* __restrict__ out)
{
    extern __shared__ __align__(16) char sm[];
    gemm_tile(g_AO, wo, bo, out, nullptr, nullptr, 1.0f, blockIdx.y * BM, blockIdx.x * BN, sm);
}

// ---------------------------------------------------------------------------
// Tensor-core flash attention.
// Grid: (N/128 = 16, B*H = 32). 256 threads = 8 warps x 16 q-rows.
// SMEM: Qhi,Qlo | 2 stages of {Khi,Klo,Vhi,Vlo}; pitch 144 B per 64-bf16 row.
// ---------------------------------------------------------------------------
__device__ __forceinline__ void issue_kv(uint32_t dstbase, int tid,
                                         const __nv_bfloat16* kh, const __nv_bfloat16* kl,
                                         const __nv_bfloat16* vh, const __nv_bfloat16* vl)
{
    #pragma unroll
    for (int l = 0; l < 4; l++) {
        int cid = tid + l * 256;
        int row = cid >> 3, c8 = cid & 7;
        uint32_t off = (uint32_t)(row * APITCH + c8 * 16);
        const size_t g = (size_t)row * 64 + c8 * 8;
        cpa16(dstbase + off,             kh + g);
        cpa16(dstbase + AHALF + off,     kl + g);
        cpa16(dstbase + 2 * AHALF + off, vh + g);
        cpa16(dstbase + 3 * AHALF + off, vl + g);
    }
}

__global__ __launch_bounds__(256, 1)
void mha_attn_tc_kernel()
{
    extern __shared__ __align__(16) char sm[];
    const uint32_t sb = smem_u32(sm);
    const int tid = threadIdx.x;
    const int lane = tid & 31;
    const int wid = tid >> 5;
    const int bh = blockIdx.y;
    const int qt = blockIdx.x;

    const size_t hbase = (size_t)bh * N_ * D_;
    // Load Q tile (hi/lo) into SMEM
    {
        const __nv_bfloat16* qh = g_Qhi + hbase + (size_t)qt * 128 * D_;
        const __nv_bfloat16* ql = g_Qlo + hbase + (size_t)qt * 128 * D_;
        #pragma unroll
        for (int l = 0; l < 4; l++) {
            int cid = tid + l * 256;
            int row = cid >> 3, c8 = cid & 7;
            const size_t g = (size_t)row * 64 + c8 * 8;
            uint32_t off = (uint32_t)(row * APITCH + c8 * 16);
            *reinterpret_cast<uint4*>(sm + off) = *reinterpret_cast<const uint4*>(qh + g);
            *reinterpret_cast<uint4*>(sm + AHALF + off) = *reinterpret_cast<const uint4*>(ql + g);
        }
    }

    issue_kv(sb + 2 * AHALF, tid, g_Khi + hbase, g_Klo + hbase, g_Vhi + hbase, g_Vlo + hbase);
    cp_commit();

    float mA = -1e30f, mB = -1e30f, lA = 0.0f, lB = 0.0f;
    float oacc[8][4] = {};

    const uint32_t qrow = sb + (uint32_t)((wid * 16 + (lane & 15)) * APITCH + (lane >> 4) * 16);
    const uint32_t krow = (uint32_t)((((lane & 7) | ((lane & 16) >> 1)) * APITCH) + (lane & 8) * 2);
    const uint32_t vrow = (uint32_t)((lane & 15) * APITCH + (lane >> 4) * 16);

    for (int kt = 0; kt < 16; ++kt) {
        if (kt + 1 < 16) {
            issue_kv(sb + 2 * AHALF + (uint32_t)((kt + 1) & 1) * KV_STAGE, tid,
                     g_Khi + hbase + (size_t)(kt + 1) * 128 * D_,
                     g_Klo + hbase + (size_t)(kt + 1) * 128 * D_,
                     g_Vhi + hbase + (size_t)(kt + 1) * 128 * D_,
                     g_Vlo + hbase + (size_t)(kt + 1) * 128 * D_);
            cp_commit();
            cp_wait<1>();
        } else {
            cp_wait<0>();
        }
        __syncthreads();

        const uint32_t kb = sb + 2 * AHALF + (uint32_t)(kt & 1) * KV_STAGE;
        const uint32_t Khs = kb, Kls = kb + AHALF, Vhs = kb + 2 * AHALF, Vls = kb + 3 * AHALF;

        // S = Qs @ Ks^T  (log2-domain scores; Q pre-scaled by scale*log2e)
        float sacc[16][4] = {};
        #pragma unroll
        for (int ks = 0; ks < 4; ++ks) {
            uint32_t ah[4], al[4];
            ldm_x4(ah, qrow + ks * 32);
            ldm_x4(al, qrow + AHALF + ks * 32);
            #pragma unroll
            for (int t = 0; t < 8; ++t) {
                uint32_t bh4[4], bl4[4];
                ldm_x4(bh4, Khs + krow + t * 16 * APITCH + ks * 32);
                ldm_x4(bl4, Kls + krow + t * 16 * APITCH + ks * 32);
                #pragma unroll
                for (int sub = 0; sub < 2; ++sub) {
                    float* c = sacc[t * 2 + sub];
                    mma16816(c, ah, &bh4[2 * sub]);
                    mma16816(c, ah, &bl4[2 * sub]);
                    mma16816(c, al, &bh4[2 * sub]);
                }
            }
        }

        // Online softmax (base-2 domain)
        float tA = -1e30f, tB = -1e30f;
        #pragma unroll
        for (int f = 0; f < 16; ++f) {
            tA = fmaxf(tA, fmaxf(sacc[f][0], sacc[f][1]));
            tB = fmaxf(tB, fmaxf(sacc[f][2], sacc[f][3]));
        }
        tA = fmaxf(tA, __shfl_xor_sync(0xffffffffu, tA, 1));
        tA = fmaxf(tA, __shfl_xor_sync(0xffffffffu, tA, 2));
        tB = fmaxf(tB, __shfl_xor_sync(0xffffffffu, tB, 1));
        tB = fmaxf(tB, __shfl_xor_sync(0xffffffffu, tB, 2));
        const float nmA = fmaxf(mA, tA), nmB = fmaxf(mB, tB);
        const float cA = ex2f(mA - nmA), cB = ex2f(mB - nmB);
        mA = nmA; mB = nmB;

        float psA = 0.0f, psB = 0.0f;
        #pragma unroll
        for (int f = 0; f < 16; ++f) {
            float p0 = ex2f(sacc[f][0] - mA);
            float p1 = ex2f(sacc[f][1] - mA);
            float p2 = ex2f(sacc[f][2] - mB);
            float p3 = ex2f(sacc[f][3] - mB);
            sacc[f][0] = p0; sacc[f][1] = p1; sacc[f][2] = p2; sacc[f][3] = p3;
            psA += p0 + p1; psB += p2 + p3;
        }
        lA = lA * cA + psA;
        lB = lB * cB + psB;
        #pragma unroll
        for (int nf = 0; nf < 8; ++nf) {
            oacc[nf][0] *= cA; oacc[nf][1] *= cA;
            oacc[nf][2] *= cB; oacc[nf][3] *= cB;
        }

        // O += P @ V
        #pragma unroll
        for (int ks = 0; ks < 8; ++ks) {
            uint32_t phi[4], plo[4];
            split2(sacc[2 * ks][0],     sacc[2 * ks][1],     phi[0], plo[0]);
            split2(sacc[2 * ks][2],     sacc[2 * ks][3],     phi[1], plo[1]);
            split2(sacc[2 * ks + 1][0], sacc[2 * ks + 1][1], phi[2], plo[2]);
            split2(sacc[2 * ks + 1][2], sacc[2 * ks + 1][3], phi[3], plo[3]);
            const uint32_t vb = vrow + (uint32_t)(16 * ks * APITCH);
            #pragma unroll
            for (int dg = 0; dg < 4; ++dg) {
                uint32_t vh4[4], vl4[4];
                ldm_x4_t(vh4, Vhs + vb + dg * 32);
                ldm_x4_t(vl4, Vls + vb + dg * 32);
                mma16816(oacc[2 * dg],     phi, &vh4[0]);
                mma16816(oacc[2 * dg + 1], phi, &vh4[2]);
                mma16816(oacc[2 * dg],     phi, &vl4[0]);
                mma16816(oacc[2 * dg + 1], phi, &vl4[2]);
                mma16816(oacc[2 * dg],     plo, &vh4[0]);
                mma16816(oacc[2 * dg + 1], plo, &vh4[2]);
            }
        }
        __syncthreads();
    }

    // Epilogue
    lA += __shfl_xor_sync(0xffffffffu, lA, 1);
    lA += __shfl_xor_sync(0xffffffffu, lA, 2);
    lB += __shfl_xor_sync(0xffffffffu, lB, 1);
    lB += __shfl_xor_sync(0xffffffffu, lB, 2);
    const float iA = 1.0f / lA, iB = 1.0f / lB;

    const int b = bh >> 4;
    const int h = bh & 15;
    const int rowA = qt * 128 + wid * 16 + (lane >> 2);
    #pragma unroll
    for (int nf = 0; nf < 8; ++nf) {
        const int d0 = nf * 8 + (lane & 3) * 2;
        float2 vA = make_float2(oacc[nf][0] * iA, oacc[nf][1] * iA);
        float2 vB = make_float2(oacc[nf][2] * iB, oacc[nf][3] * iB);
        *reinterpret_cast<float2*>(&g_AO[(size_t)(b * N_ + rowA) * C_ + h * 64 + d0]) = vA;
        *reinterpret_cast<float2*>(&g_AO[(size_t)(b * N_ + rowA + 8) * C_ + h * 64 + d0]) = vB;
    }
}

// ---------------------------------------------------------------------------
extern "C" void kernel_launch(void* const* d_in, const int* in_sizes, int n_in,
                              void* d_out, int out_size)
{
    (void)in_sizes; (void)n_in; (void)out_size;
    const float* q  = (const float*)d_in[0];
    const float* k  = (const float*)d_in[1];
    const float* v  = (const float*)d_in[2];
    const float* wq = (const float*)d_in[3];
    const float* bq = (const float*)d_in[4];
    const float* wk = (const float*)d_in[5];
    const float* bk = (const float*)d_in[6];
    const float* wv = (const float*)d_in[7];
    const float* bv = (const float*)d_in[8];
    const float* wo = (const float*)d_in[9];
    const float* bo = (const float*)d_in[10];
    float* out = (float*)d_out;

    cudaFuncSetAttribute(mha_qkv_proj_kernel,
                         cudaFuncAttributeMaxDynamicSharedMemorySize, GEMM_SMEM);
    cudaFuncSetAttribute(mha_out_proj_kernel,
                         cudaFuncAttributeMaxDynamicSharedMemorySize, GEMM_SMEM);
    cudaFuncSetAttribute(mha_attn_tc_kernel,
                         cudaFuncAttributeMaxDynamicSharedMemorySize, ATTN_SMEM);

    dim3 gproj(C_ / BN, (B_ * N_) / BM, 3);
    mha_qkv_proj_kernel<<<gproj, 256, GEMM_SMEM>>>(q, k, v, wq, bq, wk, bk, wv, bv);

    dim3 gattn(N_ / 128, B_ * H_);   // 16 x 32
    mha_attn_tc_kernel<<<gattn, 256, ATTN_SMEM>>>();

    dim3 gout(C_ / BN, (B_ * N_) / BM);
    mha_out_proj_kernel<<<gout, 256, GEMM_SMEM>>>(wo, bo, out);
}